// round 1
// baseline (speedup 1.0000x reference)
#include <cuda_runtime.h>
#include <cuda_fp16.h>
#include <cstdint>

#define C 64
#define D 512
#define TEMP_INV 10.0f
#define GLW 0.5f

// ---------------- device globals (scratch; no allocation allowed) ----------------
__device__ float  g_sums[C * D];
__device__ int    g_counts[C];
__device__ __half g_cent[C * D];
__device__ float  g_loss[2];

// ---------------- K0: zero accumulators ----------------
__global__ void k_zero() {
    int i = blockIdx.x * blockDim.x + threadIdx.x;
    if (i < C * D) g_sums[i] = 0.f;
    if (i < C)     g_counts[i] = 0;
    if (i < 2)     g_loss[i] = 0.f;
}

// ---------------- K1: label histogram ----------------
__global__ void k_hist(const int* __restrict__ labels, int n) {
    __shared__ int h[C];
    int t = threadIdx.x;
    if (t < C) h[t] = 0;
    __syncthreads();
    for (int i = blockIdx.x * blockDim.x + t; i < n; i += gridDim.x * blockDim.x)
        atomicAdd(&h[labels[i]], 1);
    __syncthreads();
    if (t < C) atomicAdd(&g_counts[t], h[t]);
}

// ---------------- K2: centroid partial sums ----------------
// Grid = 16 column-slices x 32 row-chunks = 512 blocks, 512 threads.
// Each warp owns a PRIVATE shared copy of sums[64][32] -> no shared atomics.
#define P1_THREADS 512
#define P1_COLS 32
#define P1_ROWCHUNKS 32
__global__ __launch_bounds__(P1_THREADS)
void k_csum(const float* __restrict__ S1, const int* __restrict__ labels, int n) {
    extern __shared__ float priv[];  // [16 warps][C][32] = 128 KB
    int tid = threadIdx.x, w = tid >> 5, lane = tid & 31;
    int colbase = (blockIdx.x & 15) * P1_COLS;
    int chunk = blockIdx.x >> 4;
    int rows_per_block = n / P1_ROWCHUNKS;           // 2048
    int rows_per_warp  = rows_per_block / 16;        // 128
    int r0 = chunk * rows_per_block + w * rows_per_warp;
    float* my = priv + w * (C * P1_COLS);

    for (int i = tid; i < 16 * C * P1_COLS; i += P1_THREADS) priv[i] = 0.f;
    __syncthreads();

    const float* base = S1 + colbase + lane;
    int r = r0;
    for (int i = 0; i < rows_per_warp; i += 4) {
        int l0 = labels[r + 0];
        int l1 = labels[r + 1];
        int l2 = labels[r + 2];
        int l3 = labels[r + 3];
        float v0 = base[(size_t)(r + 0) * D];
        float v1 = base[(size_t)(r + 1) * D];
        float v2 = base[(size_t)(r + 2) * D];
        float v3 = base[(size_t)(r + 3) * D];
        my[l0 * P1_COLS + lane] += v0;   // conflict-free: 32 consecutive words
        my[l1 * P1_COLS + lane] += v1;
        my[l2 * P1_COLS + lane] += v2;
        my[l3 * P1_COLS + lane] += v3;
        r += 4;
    }
    __syncthreads();

    for (int idx = tid; idx < C * P1_COLS; idx += P1_THREADS) {
        int c = idx / P1_COLS, col = idx % P1_COLS;
        float s = 0.f;
#pragma unroll
        for (int ww = 0; ww < 16; ww++) s += priv[ww * (C * P1_COLS) + idx];
        atomicAdd(&g_sums[c * D + colbase + col], s);
    }
}

// ---------------- K3: centroids -> fp16 ----------------
__global__ void k_cent() {
    int i = blockIdx.x * blockDim.x + threadIdx.x;
    if (i < C * D) {
        int c = i >> 9;  // /D
        float cnt = (float)g_counts[c];
        g_cent[i] = __float2half(g_sums[i] / cnt);
    }
}

// ---------------- K4: fused dual GEMM + weighted CE ----------------
// Per warp: 16 rows x 64 classes for BOTH S1 and S2 via mma.m16n8k16.
// Centroids staged in shared as half with row stride 520 (conflict-free B loads).

__device__ __forceinline__ uint32_t f2h2(const float* p) {
    float2 f = *reinterpret_cast<const float2*>(p);
    __half2 h = __float22half2_rn(f);
    return *reinterpret_cast<uint32_t*>(&h);
}

__device__ __forceinline__ void mma16816(float* c,
                                         uint32_t a0, uint32_t a1, uint32_t a2, uint32_t a3,
                                         uint32_t b0, uint32_t b1) {
    asm volatile(
        "mma.sync.aligned.m16n8k16.row.col.f32.f16.f16.f32 "
        "{%0,%1,%2,%3}, {%4,%5,%6,%7}, {%8,%9}, {%0,%1,%2,%3};\n"
        : "+f"(c[0]), "+f"(c[1]), "+f"(c[2]), "+f"(c[3])
        : "r"(a0), "r"(a1), "r"(a2), "r"(a3), "r"(b0), "r"(b1));
}

#define P2_THREADS 256
#define CENT_STRIDE_H2 260   // (512+8)/2 half2 per class row
#define CENT_SMEM_BYTES (C * 520 * 2)

__global__ __launch_bounds__(P2_THREADS, 2)
void k_main(const float* __restrict__ S1, const float* __restrict__ S2,
            const int* __restrict__ labels, const float* __restrict__ sim, int n) {
    extern __shared__ __half cent_sh[];
    __shared__ float red[8][2];

    // Stage centroids into shared (half2, padded stride)
    {
        const __half2* src = reinterpret_cast<const __half2*>(g_cent);
        __half2* dst = reinterpret_cast<__half2*>(cent_sh);
        for (int i = threadIdx.x; i < C * D / 2; i += P2_THREADS) {
            int c = i >> 8;          // 256 half2 per class
            int d2 = i & 255;
            dst[c * CENT_STRIDE_H2 + d2] = src[i];
        }
    }
    __syncthreads();

    const __half2* centh2 = reinterpret_cast<const __half2*>(cent_sh);
    int lane = threadIdx.x & 31, wid = threadIdx.x >> 5;
    int g = lane >> 2, t = lane & 3;
    int gwarp = blockIdx.x * (P2_THREADS / 32) + wid;
    int nwarps = gridDim.x * (P2_THREADS / 32);
    int ntiles = n >> 4;

    float lsum0 = 0.f, lsum1 = 0.f;

    for (int tile = gwarp; tile < ntiles; tile += nwarps) {
        int rb = tile << 4;
        const float* a1r1 = S1 + (size_t)(rb + g) * D;
        const float* a1r2 = a1r1 + 8 * D;
        const float* a2r1 = S2 + (size_t)(rb + g) * D;
        const float* a2r2 = a2r1 + 8 * D;

        float acc[2][8][4];
#pragma unroll
        for (int m = 0; m < 2; m++)
#pragma unroll
            for (int nt = 0; nt < 8; nt++)
#pragma unroll
                for (int j = 0; j < 4; j++) acc[m][nt][j] = 0.f;

#pragma unroll 4
        for (int kt = 0; kt < D / 16; kt++) {
            int k0 = kt * 16 + t * 2;
            uint32_t a0m0 = f2h2(a1r1 + k0);
            uint32_t a1m0 = f2h2(a1r2 + k0);
            uint32_t a2m0 = f2h2(a1r1 + k0 + 8);
            uint32_t a3m0 = f2h2(a1r2 + k0 + 8);
            uint32_t a0m1 = f2h2(a2r1 + k0);
            uint32_t a1m1 = f2h2(a2r2 + k0);
            uint32_t a2m1 = f2h2(a2r1 + k0 + 8);
            uint32_t a3m1 = f2h2(a2r2 + k0 + 8);
#pragma unroll
            for (int nt = 0; nt < 8; nt++) {
                int nrow = nt * 8 + g;
                const __half2* bp = centh2 + nrow * CENT_STRIDE_H2 + (k0 >> 1);
                uint32_t b0 = *reinterpret_cast<const uint32_t*>(bp);
                uint32_t b1 = *reinterpret_cast<const uint32_t*>(bp + 4);
                mma16816(acc[0][nt], a0m0, a1m0, a2m0, a3m0, b0, b1);
                mma16816(acc[1][nt], a0m1, a1m1, a2m1, a3m1, b0, b1);
            }
        }

        // Scale by 1/TEMP
#pragma unroll
        for (int m = 0; m < 2; m++)
#pragma unroll
            for (int nt = 0; nt < 8; nt++)
#pragma unroll
                for (int j = 0; j < 4; j++) acc[m][nt][j] *= TEMP_INV;

        // Rows held by this lane: r1 = rb+g (acc[.][.][0,1]), r2 = rb+8+g (acc[.][.][2,3])
        int lab0 = labels[rb + g];
        int lab1 = labels[rb + 8 + g];

        // w = mean over 16 sim values, quad-cooperative
        float4 wv0 = *reinterpret_cast<const float4*>(sim + (size_t)(rb + g) * 16 + t * 4);
        float4 wv1 = *reinterpret_cast<const float4*>(sim + (size_t)(rb + 8 + g) * 16 + t * 4);
        float w0 = wv0.x + wv0.y + wv0.z + wv0.w;
        float w1 = wv1.x + wv1.y + wv1.z + wv1.w;
        w0 += __shfl_xor_sync(0xffffffffu, w0, 1);
        w0 += __shfl_xor_sync(0xffffffffu, w0, 2);
        w1 += __shfl_xor_sync(0xffffffffu, w1, 1);
        w1 += __shfl_xor_sync(0xffffffffu, w1, 2);
        w0 *= (1.f / 16.f);
        w1 *= (1.f / 16.f);

#pragma unroll
        for (int m = 0; m < 2; m++) {
#pragma unroll
            for (int j = 0; j < 2; j++) {
                int lab = j ? lab1 : lab0;
                float w = j ? w1 : w0;
                // max over this lane's 16 logits, then quad reduce
                float mx = -1e30f;
#pragma unroll
                for (int nt = 0; nt < 8; nt++) {
                    mx = fmaxf(mx, acc[m][nt][2 * j]);
                    mx = fmaxf(mx, acc[m][nt][2 * j + 1]);
                }
                mx = fmaxf(mx, __shfl_xor_sync(0xffffffffu, mx, 1));
                mx = fmaxf(mx, __shfl_xor_sync(0xffffffffu, mx, 2));
                float s = 0.f;
#pragma unroll
                for (int nt = 0; nt < 8; nt++) {
                    s += __expf(acc[m][nt][2 * j] - mx);
                    s += __expf(acc[m][nt][2 * j + 1] - mx);
                }
                s += __shfl_xor_sync(0xffffffffu, s, 1);
                s += __shfl_xor_sync(0xffffffffu, s, 2);
                float lse = mx + __logf(s);
                // select the label logit without dynamic register indexing
                int nt_l = lab >> 3;
                int t_l = (lab >> 1) & 3;
                float sel = 0.f;
#pragma unroll
                for (int nt = 0; nt < 8; nt++) {
                    float v = (lab & 1) ? acc[m][nt][2 * j + 1] : acc[m][nt][2 * j];
                    sel += ((nt == nt_l) && (t == t_l)) ? v : 0.f;
                }
                sel += __shfl_xor_sync(0xffffffffu, sel, 1);
                sel += __shfl_xor_sync(0xffffffffu, sel, 2);
                float ce = lse - sel;
                if (t == 0) {
                    if (m == 0) lsum0 += w * ce;
                    else        lsum1 += w * ce;
                }
            }
        }
    }

    // warp reduce (non-t0 lanes hold 0)
#pragma unroll
    for (int off = 16; off > 0; off >>= 1) {
        lsum0 += __shfl_down_sync(0xffffffffu, lsum0, off);
        lsum1 += __shfl_down_sync(0xffffffffu, lsum1, off);
    }
    if (lane == 0) { red[wid][0] = lsum0; red[wid][1] = lsum1; }
    __syncthreads();
    if (threadIdx.x == 0) {
        float s0 = 0.f, s1 = 0.f;
#pragma unroll
        for (int wq = 0; wq < P2_THREADS / 32; wq++) { s0 += red[wq][0]; s1 += red[wq][1]; }
        atomicAdd(&g_loss[0], s0);
        atomicAdd(&g_loss[1], s1);
    }
}

// ---------------- K5: finalize scalar ----------------
__global__ void k_final(float* out, int n) {
    float L = g_loss[0] / (float)n;
    float G = g_loss[1] / (float)n;
    out[0] = 0.5f * ((1.f - GLW) * L + GLW * G);
}

// ---------------- launch ----------------
extern "C" void kernel_launch(void* const* d_in, const int* in_sizes, int n_in,
                              void* d_out, int out_size) {
    const float* S1 = (const float*)d_in[0];
    const float* S2 = (const float*)d_in[1];
    const int* seg = (const int*)d_in[2];
    const float* sim = (const float*)d_in[3];
    int n = in_sizes[2];  // N = 65536

    cudaFuncSetAttribute(k_csum, cudaFuncAttributeMaxDynamicSharedMemorySize,
                         16 * C * P1_COLS * (int)sizeof(float));
    cudaFuncSetAttribute(k_main, cudaFuncAttributeMaxDynamicSharedMemorySize,
                         CENT_SMEM_BYTES);

    k_zero<<<(C * D + 255) / 256, 256>>>();
    k_hist<<<128, 256>>>(seg, n);
    k_csum<<<16 * P1_ROWCHUNKS, P1_THREADS, 16 * C * P1_COLS * sizeof(float)>>>(S1, seg, n);
    k_cent<<<(C * D + 255) / 256, 256>>>();
    k_main<<<296, P2_THREADS, CENT_SMEM_BYTES>>>(S1, S2, seg, sim, n);
    k_final<<<1, 1>>>((float*)d_out, n);
}